// round 10
// baseline (speedup 1.0000x reference)
#include <cuda_runtime.h>
#include <math.h>
#include <stdio.h>

#define NROWS 32768
#define INDIM 2048
#define HID   1024
#define CSIZE 2048
#define TOPM  256
#define NCHUNK (CSIZE/128)   // 16 column-chunks of 128 codes

// Role indices: 0:h0 1:W1 2:b1 3:W2 4:b2 5:Wm 6:bm 7:Wt 8:bt 9:Wp 10:bp
//               11:Cm 12:Ct 13:Cp 14:ksw 15:ksb
struct Pack { const float* p[16]; };
struct Meta { long long n[16]; int swap_tp; };

// ------------- scratch: __device__ globals (allocation-free) -------------
__device__ int   g_role[16];
__device__ float g_stat[16];
__device__ float g_h1[(size_t)NROWS * HID];            // 128 MB
__device__ float g_H [(size_t)NROWS * HID];            // 128 MB
__device__ float g_D [3][HID * CSIZE];                 // 24 MB: D = W @ C^T per modality
__device__ float g_invn[3][CSIZE];
__device__ float g_em  [3][CSIZE];
__device__ float g_pval[3][NROWS][NCHUNK];
__device__ int   g_pidx[3][NROWS][NCHUNK];
__device__ unsigned long long g_keys[NROWS];

// =====================================================================================
// Classify: per-input mean|x| stats (deterministic), then role assignment.
// h0/ksb by unique size; W1 vs codebooks and ksw vs biases by mean|x| (>100 sigma).
// Within-class appearance order is stable across insertion/sorted hypotheses except
// the (t,p) pair, decided by host-provided swap_tp.
// =====================================================================================
__global__ void classify_kernel(Pack pk, Meta mt)
{
    __shared__ float red[256];
    int tid = threadIdx.x;
    for (int i = 0; i < 16; i++) {
        long long n = mt.n[i];
        long long cnt = n < 16384 ? n : 16384;
        float s = 0.f;
        const float* p = pk.p[i];
        for (long long j = tid; j < cnt; j += blockDim.x) s += fabsf(p[j]);
        red[tid] = s;
        __syncthreads();
        for (int o = 128; o > 0; o >>= 1) {
            if (tid < o) red[tid] += red[tid + o];
            __syncthreads();
        }
        if (tid == 0) g_stat[i] = red[0] / (float)cnt;
        __syncthreads();
    }
    if (tid == 0) {
        int big[4], nb = 0, mid[4], nm = 0, sml[6], ns = 0, ih0 = 0, iksb = 0;
        for (int i = 0; i < 16; i++) {
            long long n = mt.n[i];
            if      (n == 67108864LL) ih0 = i;
            else if (n == 2097152LL && nb < 4) big[nb++] = i;
            else if (n == 1048576LL && nm < 4) mid[nm++] = i;
            else if (n == 1024LL    && ns < 6) sml[ns++] = i;
            else if (n == 1LL)       iksb = i;
        }
        int w1 = big[0];
        for (int t = 1; t < 4; t++) if (g_stat[big[t]] < g_stat[w1]) w1 = big[t];
        int cA[3], ncv = 0;
        for (int t = 0; t < 4; t++) if (big[t] != w1) cA[ncv++] = big[t];
        int ksw = sml[0];
        for (int t = 1; t < 6; t++) if (g_stat[sml[t]] > g_stat[ksw]) ksw = sml[t];
        int bA[5], nbv = 0;
        for (int t = 0; t < 6; t++) if (sml[t] != ksw) bA[nbv++] = sml[t];

        int sw = mt.swap_tp;
        g_role[0]  = ih0;
        g_role[1]  = w1;
        g_role[2]  = bA[0];                 // b1
        g_role[3]  = mid[0];                // W2
        g_role[4]  = bA[1];                 // b2
        g_role[5]  = mid[1];                // Wm
        g_role[6]  = bA[2];                 // bm
        g_role[7]  = sw ? mid[3] : mid[2];  // Wt
        g_role[8]  = sw ? bA[4]  : bA[3];   // bt
        g_role[9]  = sw ? mid[2] : mid[3];  // Wp
        g_role[10] = sw ? bA[3]  : bA[4];   // bp
        g_role[11] = cA[0];                 // Cm
        g_role[12] = sw ? cA[2] : cA[1];    // Ct
        g_role[13] = sw ? cA[1] : cA[2];    // Cp
        g_role[14] = ksw;
        g_role[15] = iksb;
    }
}

// =====================================================================================
// MLP GEMM: dst = relu(A @ W + bias).  128x128x16 tile, 256 threads, 8x8 per thread.
// =====================================================================================
__global__ void __launch_bounds__(256) mlp_gemm(Pack pk, int which, int K)
{
    const float* A    = which ? g_h1 : pk.p[g_role[0]];
    const float* W    = pk.p[g_role[which ? 3 : 1]];
    const float* bias = pk.p[g_role[which ? 4 : 2]];
    float*       Cd   = which ? g_H : g_h1;

    __shared__ float As[16][132];
    __shared__ float Bs[16][132];

    int tid = threadIdx.x;
    int tx = tid & 15, ty = tid >> 4;
    int bm = blockIdx.y * 128;
    int bn = blockIdx.x * 128;

    float acc[8][8] = {};

    for (int kt = 0; kt < K; kt += 16) {
        #pragma unroll
        for (int i = 0; i < 2; i++) {
            int f = tid + i * 256;
            int m = f >> 2, k4 = (f & 3) << 2;
            float4 v = *(const float4*)(A + (size_t)(bm + m) * K + kt + k4);
            As[k4 + 0][m] = v.x; As[k4 + 1][m] = v.y;
            As[k4 + 2][m] = v.z; As[k4 + 3][m] = v.w;
        }
        #pragma unroll
        for (int i = 0; i < 2; i++) {
            int f = tid + i * 256;
            int k = f >> 5, n4 = (f & 31) << 2;
            *(float4*)(&Bs[k][n4]) =
                *(const float4*)(W + (size_t)(kt + k) * HID + bn + n4);
        }
        __syncthreads();

        #pragma unroll
        for (int k = 0; k < 16; k++) {
            float a[8], b[8];
            *(float4*)(a)     = *(const float4*)(&As[k][ty * 8]);
            *(float4*)(a + 4) = *(const float4*)(&As[k][ty * 8 + 4]);
            *(float4*)(b)     = *(const float4*)(&Bs[k][tx * 8]);
            *(float4*)(b + 4) = *(const float4*)(&Bs[k][tx * 8 + 4]);
            #pragma unroll
            for (int i = 0; i < 8; i++)
                #pragma unroll
                for (int j = 0; j < 8; j++)
                    acc[i][j] = fmaf(a[i], b[j], acc[i][j]);
        }
        __syncthreads();
    }

    #pragma unroll
    for (int i = 0; i < 8; i++) {
        int row = bm + ty * 8 + i;
        #pragma unroll
        for (int j4 = 0; j4 < 8; j4 += 4) {
            float4 o; float* op = (float*)&o;
            #pragma unroll
            for (int j = 0; j < 4; j++) {
                float v = acc[i][j4 + j] + bias[bn + tx * 8 + j4 + j];
                op[j] = fmaxf(v, 0.f);
            }
            *(float4*)(Cd + (size_t)row * HID + bn + tx * 8 + j4) = o;
        }
    }
}

// =====================================================================================
// D = W @ C^T  (D[j,c] = sum_k W[j,k]*C[c,k]).  M=HID, N=CSIZE, K=HID.
// =====================================================================================
__global__ void __launch_bounds__(256) wct_gemm(Pack pk, int mod)
{
    const float* W  = pk.p[g_role[5 + 2 * mod]];
    const float* Cb = pk.p[g_role[11 + mod]];

    __shared__ float As[16][132];
    __shared__ float Bs[16][132];

    int tid = threadIdx.x;
    int tx = tid & 15, ty = tid >> 4;
    int bm = blockIdx.y * 128;
    int bn = blockIdx.x * 128;

    float acc[8][8] = {};

    for (int kt = 0; kt < HID; kt += 16) {
        #pragma unroll
        for (int i = 0; i < 2; i++) {
            int f = tid + i * 256;
            int m = f >> 2, k4 = (f & 3) << 2;
            float4 v = *(const float4*)(W + (size_t)(bm + m) * HID + kt + k4);
            As[k4 + 0][m] = v.x; As[k4 + 1][m] = v.y;
            As[k4 + 2][m] = v.z; As[k4 + 3][m] = v.w;
        }
        #pragma unroll
        for (int i = 0; i < 2; i++) {
            int f = tid + i * 256;
            int c = f >> 2, k4 = (f & 3) << 2;
            float4 v = *(const float4*)(Cb + (size_t)(bn + c) * HID + kt + k4);
            Bs[k4 + 0][c] = v.x; Bs[k4 + 1][c] = v.y;
            Bs[k4 + 2][c] = v.z; Bs[k4 + 3][c] = v.w;
        }
        __syncthreads();

        #pragma unroll
        for (int k = 0; k < 16; k++) {
            float a[8], b[8];
            *(float4*)(a)     = *(const float4*)(&As[k][ty * 8]);
            *(float4*)(a + 4) = *(const float4*)(&As[k][ty * 8 + 4]);
            *(float4*)(b)     = *(const float4*)(&Bs[k][tx * 8]);
            *(float4*)(b + 4) = *(const float4*)(&Bs[k][tx * 8 + 4]);
            #pragma unroll
            for (int i = 0; i < 8; i++)
                #pragma unroll
                for (int j = 0; j < 8; j++)
                    acc[i][j] = fmaf(a[i], b[j], acc[i][j]);
        }
        __syncthreads();
    }

    #pragma unroll
    for (int i = 0; i < 8; i++) {
        int row = bm + ty * 8 + i;
        #pragma unroll
        for (int j4 = 0; j4 < 8; j4 += 4) {
            float4 o; float* op = (float*)&o;
            #pragma unroll
            for (int j = 0; j < 4; j++) op[j] = acc[i][j4 + j];
            *(float4*)(&g_D[mod][(size_t)row * CSIZE + bn + tx * 8 + j4]) = o;
        }
    }
}

// =====================================================================================
// Per-code prep: invn[c] = 1/sqrt(||C_c||^2 + 1e-12), em[c] = b . C_c.
// =====================================================================================
__global__ void prep_kernel(Pack pk, int mod)
{
    const float* Cb   = pk.p[g_role[11 + mod]];
    const float* bvec = pk.p[g_role[6 + 2 * mod]];

    int row  = (blockIdx.x * blockDim.x + threadIdx.x) >> 5;
    int lane = threadIdx.x & 31;
    if (row >= CSIZE) return;
    const float* c = Cb + (size_t)row * HID;
    float s = 0.f, e = 0.f;
    for (int i = lane; i < HID; i += 32) {
        float cv = c[i];
        s = fmaf(cv, cv, s);
        e = fmaf(bvec[i], cv, e);
    }
    #pragma unroll
    for (int o = 16; o > 0; o >>= 1) {
        s += __shfl_xor_sync(0xFFFFFFFFu, s, o);
        e += __shfl_xor_sync(0xFFFFFFFFu, e, o);
    }
    if (lane == 0) {
        g_invn[mod][row] = 1.0f / sqrtf(s + 1e-12f);
        g_em[mod][row]   = e;
    }
}

// =====================================================================================
// VQ GEMM + argmax epilogue: S = g_H @ g_D[mod]; best (S+em[c])*invn[c] per row/chunk.
// argmin(cosine distance) == this argmax (z's own norm is a positive row scalar).
// =====================================================================================
__global__ void __launch_bounds__(256) vq_gemm(int mod)
{
    __shared__ float As[16][132];
    __shared__ float Bs[16][132];
    __shared__ float rv[128][17];
    __shared__ int   ri[128][17];

    int tid = threadIdx.x;
    int tx = tid & 15, ty = tid >> 4;
    int bm = blockIdx.y * 128;
    int bn = blockIdx.x * 128;
    const float* D = g_D[mod];

    float acc[8][8] = {};

    for (int kt = 0; kt < HID; kt += 16) {
        #pragma unroll
        for (int i = 0; i < 2; i++) {
            int f = tid + i * 256;
            int m = f >> 2, k4 = (f & 3) << 2;
            float4 v = *(const float4*)(g_H + (size_t)(bm + m) * HID + kt + k4);
            As[k4 + 0][m] = v.x; As[k4 + 1][m] = v.y;
            As[k4 + 2][m] = v.z; As[k4 + 3][m] = v.w;
        }
        #pragma unroll
        for (int i = 0; i < 2; i++) {
            int f = tid + i * 256;
            int k = f >> 5, n4 = (f & 31) << 2;
            *(float4*)(&Bs[k][n4]) =
                *(const float4*)(D + (size_t)(kt + k) * CSIZE + bn + n4);
        }
        __syncthreads();

        #pragma unroll
        for (int k = 0; k < 16; k++) {
            float a[8], b[8];
            *(float4*)(a)     = *(const float4*)(&As[k][ty * 8]);
            *(float4*)(a + 4) = *(const float4*)(&As[k][ty * 8 + 4]);
            *(float4*)(b)     = *(const float4*)(&Bs[k][tx * 8]);
            *(float4*)(b + 4) = *(const float4*)(&Bs[k][tx * 8 + 4]);
            #pragma unroll
            for (int i = 0; i < 8; i++)
                #pragma unroll
                for (int j = 0; j < 8; j++)
                    acc[i][j] = fmaf(a[i], b[j], acc[i][j]);
        }
        __syncthreads();
    }

    #pragma unroll
    for (int i = 0; i < 8; i++) {
        float bv = -INFINITY; int bi = 0;
        #pragma unroll
        for (int j = 0; j < 8; j++) {
            int c = bn + tx * 8 + j;
            float v = (acc[i][j] + g_em[mod][c]) * g_invn[mod][c];
            if (v > bv) { bv = v; bi = c; }   // j ascending: strict > keeps lowest idx
        }
        rv[ty * 8 + i][tx] = bv;
        ri[ty * 8 + i][tx] = bi;
    }
    __syncthreads();

    if (tid < 128) {
        float best = rv[tid][0]; int bidx = ri[tid][0];
        #pragma unroll
        for (int t = 1; t < 16; t++) {
            float v = rv[tid][t];
            if (v > best) { best = v; bidx = ri[tid][t]; }
        }
        g_pval[mod][bm + tid][blockIdx.x] = best;
        g_pidx[mod][bm + tid][blockIdx.x] = bidx;
    }
}

// =====================================================================================
// Final per-row argmax across chunks; write codes [N,3] as FLOAT32 at out[0:N*3].
// (Output dtype is float32: integer outputs are exactly representable.)
// =====================================================================================
__global__ void reduce_codes(float* __restrict__ out)
{
    int n = blockIdx.x * blockDim.x + threadIdx.x;
    if (n >= NROWS) return;
    #pragma unroll
    for (int m = 0; m < 3; m++) {
        float bv = g_pval[m][n][0]; int bi = g_pidx[m][n][0];
        #pragma unroll
        for (int c = 1; c < NCHUNK; c++) {
            float v = g_pval[m][n][c];
            if (v > bv) { bv = v; bi = g_pidx[m][n][c]; }
        }
        out[n * 3 + m] = (float)bi;
    }
}

// =====================================================================================
// Key-token score -> orderable 64-bit key (sigmoid monotone -> rank raw logit)
// =====================================================================================
__global__ void score_kernel(Pack pk)
{
    const float* ksw = pk.p[g_role[14]];
    const float* ksb = pk.p[g_role[15]];
    int warp = (blockIdx.x * blockDim.x + threadIdx.x) >> 5;
    int lane = threadIdx.x & 31;
    if (warp >= NROWS) return;
    const float* h = g_H + (size_t)warp * HID;
    double s = 0.0;
    for (int i = lane; i < HID; i += 32) s += (double)h[i] * (double)ksw[i];
    #pragma unroll
    for (int o = 16; o > 0; o >>= 1) s += __shfl_xor_sync(0xFFFFFFFFu, s, o);
    if (lane == 0) {
        float sc = (float)(s + (double)ksb[0]);
        unsigned int b = __float_as_uint(sc);
        b = (b & 0x80000000u) ? ~b : (b | 0x80000000u);   // totally-ordered float bits
        g_keys[warp] = ((unsigned long long)b << 32) | (0xFFFFFFFFu - (unsigned)warp);
    }
}

// =====================================================================================
// Exact top-256 via radix select + bitonic sort; writes key_idx and gathered codes
// as FLOAT32 at out[N*3 : N*3+256] and out[N*3+256 : N*3+256+768].
// =====================================================================================
__global__ void topk_kernel(float* __restrict__ out)
{
    __shared__ unsigned int hist[256];
    __shared__ unsigned long long sprefix;
    __shared__ int skk;
    __shared__ unsigned long long skeys[TOPM];
    __shared__ unsigned int scount;

    int tid = threadIdx.x;
    if (tid == 0) { sprefix = 0ULL; skk = TOPM; scount = 0u; }
    __syncthreads();

    for (int p = 7; p >= 0; p--) {
        if (tid < 256) hist[tid] = 0u;
        __syncthreads();
        unsigned long long pref = sprefix;
        for (int i = tid; i < NROWS; i += blockDim.x) {
            unsigned long long k = g_keys[i];
            bool match = (p == 7) || ((k >> ((p + 1) * 8)) == pref);
            if (match) atomicAdd(&hist[(unsigned)(k >> (p * 8)) & 0xFFu], 1u);
        }
        __syncthreads();
        if (tid == 0) {
            int kk = skk, c = 0, d;
            for (d = 255; d >= 0; d--) { c += (int)hist[d]; if (c >= kk) break; }
            skk = kk - (c - (int)hist[d]);
            sprefix = (sprefix << 8) | (unsigned long long)d;
        }
        __syncthreads();
    }
    unsigned long long thr = sprefix;   // exact 256th-largest key (keys unique)

    for (int i = tid; i < NROWS; i += blockDim.x) {
        unsigned long long k = g_keys[i];
        if (k >= thr) {
            unsigned p = atomicAdd(&scount, 1u);
            if (p < TOPM) skeys[p] = k;
        }
    }
    __syncthreads();

    for (int sz = 2; sz <= TOPM; sz <<= 1) {
        for (int st = sz >> 1; st > 0; st >>= 1) {
            __syncthreads();
            if (tid < TOPM) {
                int ixj = tid ^ st;
                if (ixj > tid) {
                    unsigned long long a = skeys[tid], b = skeys[ixj];
                    bool descBlk = ((tid & sz) == 0);
                    if (descBlk ? (a < b) : (a > b)) { skeys[tid] = b; skeys[ixj] = a; }
                }
            }
        }
    }
    __syncthreads();

    if (tid < TOPM) {
        unsigned idx = 0xFFFFFFFFu - (unsigned)(skeys[tid] & 0xFFFFFFFFu);
        out[NROWS * 3 + tid] = (float)idx;
        #pragma unroll
        for (int m = 0; m < 3; m++)
            out[NROWS * 3 + TOPM + tid * 3 + m] = out[(size_t)idx * 3 + m];
    }
}

// =====================================================================================
extern "C" void kernel_launch(void* const* d_in, const int* in_sizes, int n_in,
                              void* d_out, int out_size)
{
    Pack pk;
    Meta mt;
    int n16 = n_in < 16 ? n_in : 16;

    // --- diagnostics (host-only; runs on correctness+capture calls, not replays) ---
    fprintf(stderr, "[diag] n_in=%d out_size=%d sizes:", n_in, out_size);
    for (int i = 0; i < n16; i++) fprintf(stderr, " %d", in_sizes[i]);
    fprintf(stderr, "\n");

    // bytes-vs-elements: ksb is 1 element; if the smallest size is 4, sizes are bytes.
    long long mn = 0x7FFFFFFFFFFFFFFFLL;
    for (int i = 0; i < n16; i++) {
        long long s = (long long)in_sizes[i];
        if (s < mn) mn = s;
    }
    long long div = (mn == 4) ? 4 : 1;

    for (int i = 0; i < 16; i++) {
        int src = i < n16 ? i : (n16 - 1);
        pk.p[i] = (const float*)d_in[src];
        mt.n[i] = (long long)in_sizes[src] / div;
    }

    // t/p appearance order: name-sorted metadata lists p before t -> swap;
    // insertion / size-sorted patterns keep t before p -> no swap.
    mt.swap_tp = 0;
    if (mt.n[13] == 67108864LL) mt.swap_tp = 1;                          // case-sensitive sort
    else if (mt.n[8] == 67108864LL && mt.n[0] == 1024LL) mt.swap_tp = 1; // case-insensitive sort

    float* out = (float*)d_out;

    dim3 blk(256);
    dim3 gMLP(HID / 128,  NROWS / 128);   // (8, 256)
    dim3 gWCT(CSIZE / 128, HID / 128);    // (16, 8)
    dim3 gVQ (CSIZE / 128, NROWS / 128);  // (16, 256)

    // 0) resolve input roles on-device (deterministic -> graph-safe)
    classify_kernel<<<1, 256>>>(pk, mt);

    // 1) encoder MLP
    mlp_gemm<<<gMLP, blk>>>(pk, 0, INDIM);
    mlp_gemm<<<gMLP, blk>>>(pk, 1, HID);

    // 2) folded projection @ codebook: D = W @ C^T, em = b.C, invn = 1/||C||
    wct_gemm<<<gWCT, blk>>>(pk, 0);
    wct_gemm<<<gWCT, blk>>>(pk, 1);
    wct_gemm<<<gWCT, blk>>>(pk, 2);
    prep_kernel<<<CSIZE / 8, 256>>>(pk, 0);
    prep_kernel<<<CSIZE / 8, 256>>>(pk, 1);
    prep_kernel<<<CSIZE / 8, 256>>>(pk, 2);

    // 3) VQ argmax (partial per 128-code chunk)
    vq_gemm<<<gVQ, blk>>>(0);
    vq_gemm<<<gVQ, blk>>>(1);
    vq_gemm<<<gVQ, blk>>>(2);

    // 4) codes (float32 values)
    reduce_codes<<<NROWS / 256, 256>>>(out);

    // 5) key-token scoring + exact top-256 (+ gather), float32 values
    score_kernel<<<NROWS / 8, 256>>>(pk);
    topk_kernel<<<1, 1024>>>(out);

    fprintf(stderr, "[diag] post-launch err=%d (%s)\n",
            (int)cudaPeekAtLastError(), cudaGetErrorString(cudaPeekAtLastError()));
}